// round 17
// baseline (speedup 1.0000x reference)
#include <cuda_runtime.h>

#define V_SIZE 128000
#define V4 32000               // V_SIZE/4 quads
#define NWIN 125               // windows of 256 quads (V4/256)
#define NBY 64                 // sibling blocks per window (one per batch row)
#define WARPS_PER_WIN (NBY * 8)  // 512 reader warps per window
#define R_MAX 512
#define PEN_LAMBDA 0.5f

// Scratch (__device__ globals; zero-initialized at load).
// Invariant: every execution leaves scratch at zero (consume-and-reset).
__device__ float g_pen[V_SIZE];
__device__ float g_pen_head[NWIN * 4];   // replica of each window's first quad
__device__ float g_firing[R_MAX];
__device__ int   g_tick[NWIN];

// ---------------------------------------------------------------------------
// k_scatter: pen[token] += sigmoid(gate_logit[rule]) * lambda
// 245 blocks x 512 threads, 2 quads (8 pairs)/thread. Gates (lambda folded)
// + firing flags in smem; firing flushed once per CTA. Tokens in a window's
// first quad also add into g_pen_head (replica consumed by k_main).
// ---------------------------------------------------------------------------
__device__ __forceinline__ void scatter_one(int t, float v) {
    atomicAdd(&g_pen[t], v);
    if ((t & 1023) < 4)
        atomicAdd(&g_pen_head[((t >> 10) << 2) | (t & 3)], v);
}

__global__ void __launch_bounds__(512) k_scatter(
    const float* __restrict__ gate_logits,
    const int* __restrict__ rule_ids,
    const int* __restrict__ token_ids,
    int n_quads)   // E/4
{
    __shared__ float s_gates[R_MAX];
    __shared__ int   s_fire[R_MAX];
    int tid = threadIdx.x;
    s_gates[tid] = PEN_LAMBDA / (1.0f + __expf(-gate_logits[tid]));
    s_fire[tid] = 0;
    __syncthreads();

    #pragma unroll
    for (int p = 0; p < 2; p++) {
        int q = blockIdx.x * 1024 + p * 512 + tid;
        if (q < n_quads) {
            int4 r = reinterpret_cast<const int4*>(rule_ids)[q];
            int4 t = reinterpret_cast<const int4*>(token_ids)[q];
            scatter_one(t.x, s_gates[r.x]);
            scatter_one(t.y, s_gates[r.y]);
            scatter_one(t.z, s_gates[r.z]);
            scatter_one(t.w, s_gates[r.w]);
            s_fire[r.x] = 1;
            s_fire[r.y] = 1;
            s_fire[r.z] = 1;
            s_fire[r.w] = 1;
        }
    }
    __syncthreads();
    if (s_fire[tid]) g_firing[tid] = 1.0f;   // idempotent across CTAs
}

// ---------------------------------------------------------------------------
// k_main: barrier-free fused broadcast + penalties + loss + warp-ticketed
// reset. Grid (125, 64), 256 threads: block (bx, by) = window bx, row by.
// Per thread: 1 pen LDG.128 -> shfl-composed shifted quad -> 1 logits
// LDG.128 -> 2 STG.128. No smem, no __syncthreads.
// Each warp tickets g_tick[bx] after its stores; a ballot whose predicate
// depends on the loaded pen bits orders every lane's pen reads before the
// atomic. The 512th warp zeroes the window + next head replica + ticket.
// ---------------------------------------------------------------------------
__global__ void __launch_bounds__(256) k_main(
    const float* __restrict__ logits,
    const float* __restrict__ gate_logits,
    float* __restrict__ modified,
    float* __restrict__ penalties,   // = out + BV + 1 (4B-aligned)
    float* __restrict__ out_loss,
    int pen_quads)                   // (BV-3)/4
{
    int tid  = threadIdx.x;
    int lane = tid & 31;
    int bx   = blockIdx.x;
    int by   = blockIdx.y;
    int m    = bx * 256 + tid;              // this thread's pen quad
    int wn   = (bx + 1 == NWIN) ? 0 : bx + 1;
    const float4* pen4 = reinterpret_cast<const float4*>(g_pen);

    // own pen quad + neighbor quad (shfl; lane 31 loads it explicitly)
    float4 p = __ldg(pen4 + m);
    float4 pn;
    pn.x = __shfl_down_sync(0xFFFFFFFFu, p.x, 1);
    pn.y = __shfl_down_sync(0xFFFFFFFFu, p.y, 1);
    pn.z = __shfl_down_sync(0xFFFFFFFFu, p.z, 1);
    pn.w = __shfl_down_sync(0xFFFFFFFFu, p.w, 1);
    if (lane == 31) {
        pn = (tid == 255)
           ? *reinterpret_cast<const float4*>(&g_pen_head[wn * 4])
           : __ldg(pen4 + m + 1);
    }
    float4 ps = make_float4(p.w, pn.x, pn.y, pn.z);

    // main traffic: 1 load, 2 stores
    int i = by * V4 + m;
    float4 l = __ldg(reinterpret_cast<const float4*>(logits) + i);
    float4 o;
    o.x = l.x - p.x; o.y = l.y - p.y; o.z = l.z - p.z; o.w = l.w - p.w;
    __stcs(reinterpret_cast<float4*>(modified) + i, o);
    if (i < pen_quads)
        __stcs(reinterpret_cast<float4*>(penalties + 3) + i, ps);

    // specials
    float extra = 0.0f;
    if (bx == 0 && by == 0 && (tid >> 5) == 1) {
        // coverage loss (warp 1 of block (0,0)); reads + resets g_firing
        int lt = tid & 31;
        float f = 0.0f, gf = 0.0f;
        #pragma unroll
        for (int k = 0; k < 16; k++) {
            int r = lt + 32 * k;
            float fi = g_firing[r];
            float gi = 1.0f / (1.0f + __expf(-gate_logits[r]));
            f  += fi;
            gf += gi * fi;
            g_firing[r] = 0.0f;
        }
        #pragma unroll
        for (int off = 16; off > 0; off >>= 1) {
            gf += __shfl_down_sync(0xFFFFFFFFu, gf, off);
            f  += __shfl_down_sync(0xFFFFFFFFu, f,  off);
        }
        if (lt == 0) {
            out_loss[0] = -gf / fmaxf(f, 1.0f);
            // head scalars not covered by the aligned quad window
            float4 h = __ldg(pen4);          // pen[0..3]
            penalties[0] = h.x;
            penalties[1] = h.y;
            penalties[2] = h.z;
            extra = h.x;                     // dependency hook for the ticket
        }
    }
    if (bx == NWIN - 1 && by == NBY - 1 && tid == 255) {
        // last penalties element: pen[V-1] == p.w of this thread
        penalties[(int64_t)64 * V_SIZE - 1] = p.w;
    }

    // warp ticket: ballot predicate depends on p/pn/extra bits so every
    // lane's pen reads have completed before the atomic issues. The
    // predicate is true in practice (finite data) but not foldable.
    unsigned bits = (unsigned)__float_as_int(p.x)
                  ^ (unsigned)__float_as_int(pn.w)
                  ^ (unsigned)__float_as_int(extra);
    unsigned bal = __ballot_sync(0xFFFFFFFFu, bits != 0x7f800001u);
    int old = -1;
    if (lane == 0 && bal != 0u)
        old = atomicAdd(&g_tick[bx], 1);
    old = __shfl_sync(0xFFFFFFFFu, old, 0);

    if (old == WARPS_PER_WIN - 1) {
        // last reader warp of this window: reset for the next replay
        float4 z = make_float4(0.f, 0.f, 0.f, 0.f);
        float4* dst = reinterpret_cast<float4*>(g_pen) + bx * 256;
        #pragma unroll
        for (int k = 0; k < 8; k++)
            dst[k * 32 + lane] = z;
        if (lane == 0) {
            *reinterpret_cast<float4*>(&g_pen_head[wn * 4]) = z;
            g_tick[bx] = 0;
        }
    }
}

extern "C" void kernel_launch(void* const* d_in, const int* in_sizes, int n_in,
                              void* d_out, int out_size) {
    const float* logits      = (const float*)d_in[0];
    const float* gate_logits = (const float*)d_in[1];
    const int*   rule_ids    = (const int*)d_in[2];
    const int*   token_ids   = (const int*)d_in[3];

    int BV = in_sizes[0];       // 8,192,000
    int E  = in_sizes[2];       // 1,000,000

    float* out       = (float*)d_out;
    float* modified  = out;                 // [BV]
    float* out_loss  = out + BV;            // [1]
    float* penalties = out + BV + 1;        // [BV], 4B-aligned

    // 1) scatter (scratch arrives zeroed: initial state or previous k_main)
    {
        int n_quads = E / 4;                        // 250,000
        int blocks = (n_quads + 1023) / 1024;       // 245
        k_scatter<<<blocks, 512>>>(gate_logits, rule_ids, token_ids, n_quads);
    }
    // 2) barrier-free fused broadcast + penalties + loss + warp-ticket reset
    {
        int pen_quads = (BV - 3) / 4;               // 2,047,999
        dim3 grid(NWIN, NBY);                       // (125, 64)
        k_main<<<grid, 256>>>(logits, gate_logits, modified, penalties,
                              out_loss, pen_quads);
    }
}